// round 8
// baseline (speedup 1.0000x reference)
#include <cuda_runtime.h>

#define NA   25
#define NHW  1444
#define NV   361          // NHW / 4 (float4 units per plane)
#define HALF 181          // z=0 handles groups [0,181), z=1 handles [181,361)
#define BMAX 512

__constant__ float c_bw[5] = {1.3221f, 3.19275f, 5.05587f, 9.47112f, 11.2364f};
__constant__ float c_bh[5] = {1.73145f, 4.00944f, 8.09892f, 4.84053f, 10.0071f};
__constant__ float c_sc[5] = {0.5f, 0.75f, 1.0f, 1.25f, 1.5f};

struct BP {
    float gl, gr, gt, gb;     // gt box edges
    float garea;
    float txt, tyt, twt, tht; // coord targets at the special cell
    int   sidx, best;
};

__device__ __align__(16) float g_part[BMAX * NA * 2];
__device__ unsigned g_done = 0;

__device__ __forceinline__ float tanhapx(float x) {
    float t;
    asm("tanh.approx.f32 %0, %1;" : "=f"(t) : "f"(x));
    return t;
}
__device__ __forceinline__ float ex2apx(float x) {
    float t;
    asm("ex2.approx.f32 %0, %1;" : "=f"(t) : "f"(x));
    return t;
}

__device__ __forceinline__ unsigned atomic_inc_release(unsigned* p) {
    unsigned old;
    asm volatile("atom.release.gpu.add.u32 %0, [%1], %2;"
                 : "=r"(old) : "l"(p), "r"(1u) : "memory");
    return old;
}

struct CO { float dense, inter, uni, sx, sy, pc; };

// Per-cell evaluation. hw/hh are HALF widths (0.5*anchor folded into lhw/lhh).
__device__ __forceinline__ CO cell_eval(
    float tx, float ty, float tw, float th, float tc,
    float cxw, float cyh, float lhw, float lhh,
    float gl, float gr, float gt, float gb, float garea)
{
    const float L2E = 1.4426950408889634f;
    float tX = tanhapx(0.5f * tx);
    float tY = tanhapx(0.5f * ty);
    float tC = tanhapx(0.5f * tc);
    float bx = fmaf(tX, 0.5f, cxw);            // sigmoid(tx) + w
    float by = fmaf(tY, 0.5f, cyh);
    float hw = ex2apx(fmaf(tw, L2E, lhw));     // 0.5 * aw * exp(tw)
    float hh = ex2apx(fmaf(th, L2E, lhh));
    // intersection-direct IoU
    float rx = fminf(bx + hw, gr);
    float lx = fmaxf(bx - hw, gl);
    float ry = fminf(by + hh, gb);
    float ly = fmaxf(by - hh, gt);
    float cw = rx - lx;
    float ch = ry - ly;
    float inter = (cw > 0.0f && ch > 0.0f) ? cw * ch : 0.0f;
    float uni   = fmaf(hw * hh, 4.0f, garea) - inter;
    bool noobj  = fmaf(uni, -0.6f, inter) <= 0.0f;   // !(iou > 0.6)
    float pc = fmaf(tC, 0.5f, 0.5f);
    float confsq = noobj ? pc * pc : 0.0f;
    float s1 = fmaf(tX, tX, tY * tY);          // (2*dx)^2 + (2*dy)^2
    float s2 = fmaf(tw, tw, th * th);          // dw^2 + dh^2 (targets 0)
    CO o;
    o.dense = fmaf(s1, 0.125f, fmaf(s2, 0.5f, 0.5f * confsq));
    o.inter = inter; o.uni = uni;
    o.sx = fmaf(tX, 0.5f, 0.5f);
    o.sy = fmaf(tY, 0.5f, 0.5f);
    o.pc = pc;
    return o;
}

// process one float4 group (4 cells starting at cell index base)
__device__ __forceinline__ float group_eval(
    const float4& X, const float4& Y, const float4& W,
    const float4& H, const float4& C, int base,
    float lhw, float lhh, const BP& bp)
{
    float xa[4] = {X.x, X.y, X.z, X.w};
    float ya[4] = {Y.x, Y.y, Y.z, Y.w};
    float wa[4] = {W.x, W.y, W.z, W.w};
    float ha[4] = {H.x, H.y, H.z, H.w};
    float ca[4] = {C.x, C.y, C.z, C.w};
    float s = 0.0f;
#pragma unroll
    for (int k = 0; k < 4; k++) {
        int idx = base + k;
        int hh_ = (idx * 1725) >> 16;      // idx / 38
        int ww_ = idx - hh_ * 38;
        CO o = cell_eval(xa[k], ya[k], wa[k], ha[k], ca[k],
                         (float)ww_ + 0.5f, (float)hh_ + 0.5f,
                         lhw, lhh,
                         bp.gl, bp.gr, bp.gt, bp.gb, bp.garea);
        s += o.dense;
    }
    return s;
}

__global__ void __launch_bounds__(128) main_kernel(
    const float* __restrict__ pred, const float* __restrict__ tgt,
    float* __restrict__ out, int total)
{
    const int a = blockIdx.x;
    const int b = blockIdx.y;
    const int z = blockIdx.z;

    __shared__ BP sbp;
    __shared__ float ws[4];
    __shared__ bool isLast;

    const float4* __restrict__ p4 =
        (const float4*)(pred + (size_t)(b * NA + a) * 5 * NHW);

    const int zstart = z * HALF;                 // 0 or 181
    const int count  = HALF - z;                 // 181 or 180
    const int v  = threadIdx.x;
    const int g0 = zstart + v;                   // always < 361
    const int g1 = g0 + 128;
    const bool has1 = (v + 128 < count);

    // ---- ALL loads hoisted: 10 independent LDG.128 before any compute ----
    float4 X0 = p4[g0];
    float4 Y0 = p4[g0 + NV];
    float4 W0 = p4[g0 + 2 * NV];
    float4 H0 = p4[g0 + 3 * NV];
    float4 C0 = p4[g0 + 4 * NV];
    float4 X1, Y1, W1, H1, C1;
    if (has1) {
        X1 = p4[g1];
        Y1 = p4[g1 + NV];
        W1 = p4[g1 + 2 * NV];
        H1 = p4[g1 + 3 * NV];
        C1 = p4[g1 + 4 * NV];
    }

    if (threadIdx.x == 0) {
        float gx = tgt[4 * b + 0] * 38.0f;
        float gy = tgt[4 * b + 1] * 38.0f;
        float gw = tgt[4 * b + 2] * 38.0f;
        float gh = tgt[4 * b + 3] * 38.0f;
        int gi = (int)gx;
        int gj = (int)gy;
        float garea = gw * gh;

        // division-free argmax over anchor IoUs (first max wins)
        int best = 0;
        float binter = 0.0f, buni = 1.0f;
#pragma unroll
        for (int ai = 0; ai < NA; ai++) {
            float aw = c_bw[ai % 5] * c_sc[ai / 5];
            float ah = c_bh[ai % 5] * c_sc[ai / 5];
            float in_ = fminf(aw, gw) * fminf(ah, gh);
            float un  = aw * ah + garea - in_;
            if (ai == 0 || in_ * buni > binter * un) {
                binter = in_; buni = un; best = ai;
            }
        }
        float baw = c_bw[best % 5] * c_sc[best / 5];
        float bah = c_bh[best % 5] * c_sc[best / 5];

        BP bp;
        bp.gl = gx - 0.5f * gw;  bp.gr = gx + 0.5f * gw;
        bp.gt = gy - 0.5f * gh;  bp.gb = gy + 0.5f * gh;
        bp.garea = garea;
        bp.txt = gx - (float)gi;
        bp.tyt = gy - (float)gj;
        bp.twt = logf(gw / baw);
        bp.tht = logf(gh / bah);
        bp.sidx = gj * 38 + gi;
        bp.best = best;
        sbp = bp;
    }
    __syncthreads();
    const BP bp = sbp;

    int am = a - (a / 5) * 5;
    float aw = c_bw[am] * c_sc[a / 5];
    float ah = c_bh[am] * c_sc[a / 5];
    float lhw = __log2f(0.5f * aw);
    float lhh = __log2f(0.5f * ah);

    float acc = group_eval(X0, Y0, W0, H0, C0, 4 * g0, lhw, lhh, bp);
    if (has1)
        acc += group_eval(X1, Y1, W1, H1, C1, 4 * g1, lhw, lhh, bp);

    // special-cell correction: the block covering its group owns it
    if (threadIdx.x == 0 && a == bp.best) {
        int sg = bp.sidx >> 2;
        if (sg >= zstart && sg < zstart + count) {
            int idx = bp.sidx;
            const float* p = pred + (size_t)(b * NA + a) * 5 * NHW;
            float tx = __ldg(p + idx);
            float ty = __ldg(p + idx + NHW);
            float tw = __ldg(p + idx + 2 * NHW);
            float th = __ldg(p + idx + 3 * NHW);
            float tc = __ldg(p + idx + 4 * NHW);
            int hh_ = (idx * 1725) >> 16;
            int ww_ = idx - hh_ * 38;
            CO o = cell_eval(tx, ty, tw, th, tc,
                             (float)ww_ + 0.5f, (float)hh_ + 0.5f,
                             lhw, lhh,
                             bp.gl, bp.gr, bp.gt, bp.gb, bp.garea);
            float dx = o.sx - bp.txt;
            float dy = o.sy - bp.tyt;
            float dw = tw - bp.twt;
            float dh = th - bp.tht;
            float tconf = o.inter / o.uni;
            float dc = o.pc - tconf;
            float truec = 0.5f * (dx * dx + dy * dy + dw * dw + dh * dh)
                        + 2.5f * (dc * dc);           // OBJECT_SCALE/2
            acc += truec - o.dense;
        }
    }

    // deterministic block reduction (4 warps)
#pragma unroll
    for (int off = 16; off > 0; off >>= 1)
        acc += __shfl_down_sync(0xffffffffu, acc, off);
    if ((threadIdx.x & 31) == 0) ws[threadIdx.x >> 5] = acc;
    __syncthreads();
    if (threadIdx.x == 0) {
        g_part[(b * NA + a) * 2 + z] = (ws[0] + ws[1]) + (ws[2] + ws[3]);
        unsigned t = atomic_inc_release(&g_done);
        isLast = (t == (unsigned)(total - 1));
    }
    __syncthreads();

    // last block performs the (deterministic-order) final reduction
    if (isLast) {
        if (threadIdx.x == 0) {
            g_done = 0;          // reset for next graph replay
            __threadfence();     // single acquire-side fence, once per grid
        }
        __syncthreads();
        __shared__ double sh[128];
        const float4* __restrict__ pp = (const float4*)g_part;
        int n4 = total >> 2;
        double s = 0.0;
        for (int i = threadIdx.x; i < n4; i += 128) {
            float4 vv = __ldcg(pp + i);   // L2 reads = coherence point
            s += ((double)vv.x + (double)vv.y) + ((double)vv.z + (double)vv.w);
        }
        sh[threadIdx.x] = s;
        __syncthreads();
#pragma unroll
        for (int off = 64; off > 0; off >>= 1) {
            if (threadIdx.x < off) sh[threadIdx.x] += sh[threadIdx.x + off];
            __syncthreads();
        }
        if (threadIdx.x == 0) out[0] = (float)sh[0];
    }
}

extern "C" void kernel_launch(void* const* d_in, const int* in_sizes, int n_in,
                              void* d_out, int out_size) {
    const float* pred = (const float*)d_in[0];
    const float* tgt  = (const float*)d_in[1];
    int B = in_sizes[1] / 4;
    if (B > BMAX) B = BMAX;

    dim3 grid(NA, B, 2);
    main_kernel<<<grid, 128>>>(pred, tgt, (float*)d_out, B * NA * 2);
}

// round 9
// speedup vs baseline: 1.3775x; 1.3775x over previous
#include <cuda_runtime.h>

#define NA   25
#define NHW  1444
#define NV   361          // NHW / 4 (float4 units per plane)
#define NT   192          // threads per block: 2 groups cover 361 (169 active in g1)
#define BMAX 512

__constant__ float c_bw[5] = {1.3221f, 3.19275f, 5.05587f, 9.47112f, 11.2364f};
__constant__ float c_bh[5] = {1.73145f, 4.00944f, 8.09892f, 4.84053f, 10.0071f};
__constant__ float c_sc[5] = {0.5f, 0.75f, 1.0f, 1.25f, 1.5f};

struct BP {
    float gl, gr, gt, gb;     // gt box edges
    float garea;
    float txt, tyt, twt, tht; // coord targets at the special cell
    int   sidx, best;
};

__device__ __align__(16) float g_part[BMAX * NA];
__device__ unsigned g_done = 0;

__device__ __forceinline__ float tanhapx(float x) {
    float t;
    asm("tanh.approx.f32 %0, %1;" : "=f"(t) : "f"(x));
    return t;
}
__device__ __forceinline__ float ex2apx(float x) {
    float t;
    asm("ex2.approx.f32 %0, %1;" : "=f"(t) : "f"(x));
    return t;
}
__device__ __forceinline__ float lg2apx(float x) {
    float t;
    asm("lg2.approx.f32 %0, %1;" : "=f"(t) : "f"(x));
    return t;
}

__device__ __forceinline__ unsigned atomic_inc_release(unsigned* p) {
    unsigned old;
    asm volatile("atom.release.gpu.add.u32 %0, [%1], %2;"
                 : "=r"(old) : "l"(p), "r"(1u) : "memory");
    return old;
}

struct CO { float dense, inter, uni, sx, sy, pc; };

// Per-cell evaluation. hw/hh are HALF widths (0.5*anchor folded into lhw/lhh).
__device__ __forceinline__ CO cell_eval(
    float tx, float ty, float tw, float th, float tc,
    float cxw, float cyh, float lhw, float lhh,
    float gl, float gr, float gt, float gb, float garea)
{
    const float L2E = 1.4426950408889634f;
    float tX = tanhapx(0.5f * tx);
    float tY = tanhapx(0.5f * ty);
    float tC = tanhapx(0.5f * tc);
    float bx = fmaf(tX, 0.5f, cxw);            // sigmoid(tx) + w
    float by = fmaf(tY, 0.5f, cyh);
    float hw = ex2apx(fmaf(tw, L2E, lhw));     // 0.5 * aw * exp(tw)
    float hh = ex2apx(fmaf(th, L2E, lhh));
    // intersection-direct IoU
    float rx = fminf(bx + hw, gr);
    float lx = fmaxf(bx - hw, gl);
    float ry = fminf(by + hh, gb);
    float ly = fmaxf(by - hh, gt);
    float cw = rx - lx;
    float ch = ry - ly;
    float inter = (cw > 0.0f && ch > 0.0f) ? cw * ch : 0.0f;
    float uni   = fmaf(hw * hh, 4.0f, garea) - inter;
    bool noobj  = fmaf(uni, -0.6f, inter) <= 0.0f;   // !(iou > 0.6)
    float pc = fmaf(tC, 0.5f, 0.5f);
    float confsq = noobj ? pc * pc : 0.0f;
    float s1 = fmaf(tX, tX, tY * tY);          // (2*dx)^2 + (2*dy)^2
    float s2 = fmaf(tw, tw, th * th);          // dw^2 + dh^2 (targets 0)
    CO o;
    o.dense = fmaf(s1, 0.125f, fmaf(s2, 0.5f, 0.5f * confsq));
    o.inter = inter; o.uni = uni;
    o.sx = fmaf(tX, 0.5f, 0.5f);
    o.sy = fmaf(tY, 0.5f, 0.5f);
    o.pc = pc;
    return o;
}

// process one float4 group (4 cells starting at cell index base)
__device__ __forceinline__ float group_eval(
    const float4& X, const float4& Y, const float4& W,
    const float4& H, const float4& C, int base,
    float lhw, float lhh, const BP& bp)
{
    float xa[4] = {X.x, X.y, X.z, X.w};
    float ya[4] = {Y.x, Y.y, Y.z, Y.w};
    float wa[4] = {W.x, W.y, W.z, W.w};
    float ha[4] = {H.x, H.y, H.z, H.w};
    float ca[4] = {C.x, C.y, C.z, C.w};
    float s = 0.0f;
#pragma unroll
    for (int k = 0; k < 4; k++) {
        int idx = base + k;
        int hh_ = (idx * 1725) >> 16;      // idx / 38
        int ww_ = idx - hh_ * 38;
        CO o = cell_eval(xa[k], ya[k], wa[k], ha[k], ca[k],
                         (float)ww_ + 0.5f, (float)hh_ + 0.5f,
                         lhw, lhh,
                         bp.gl, bp.gr, bp.gt, bp.gb, bp.garea);
        s += o.dense;
    }
    return s;
}

__global__ void __launch_bounds__(NT) main_kernel(
    const float* __restrict__ pred, const float* __restrict__ tgt,
    float* __restrict__ out, int total)
{
    const int a = blockIdx.x;
    const int b = blockIdx.y;

    __shared__ BP sbp;
    __shared__ float ws[6];
    __shared__ bool isLast;

    const float4* __restrict__ p4 =
        (const float4*)(pred + (size_t)(b * NA + a) * 5 * NHW);

    const int v  = threadIdx.x;           // group0 index, always < 361
    const int g1 = v + NT;                // group1 index
    const bool has1 = (g1 < NV);          // 169 of 192 threads

    // ---- ALL loads hoisted: up to 10 independent LDG.128 before compute ----
    float4 X0 = p4[v];
    float4 Y0 = p4[v + NV];
    float4 W0 = p4[v + 2 * NV];
    float4 H0 = p4[v + 3 * NV];
    float4 C0 = p4[v + 4 * NV];
    float4 X1, Y1, W1, H1, C1;
    if (has1) {
        X1 = p4[g1];
        Y1 = p4[g1 + NV];
        W1 = p4[g1 + 2 * NV];
        H1 = p4[g1 + 3 * NV];
        C1 = p4[g1 + 4 * NV];
    }

    if (threadIdx.x == 0) {
        float gx = tgt[4 * b + 0] * 38.0f;
        float gy = tgt[4 * b + 1] * 38.0f;
        float gw = tgt[4 * b + 2] * 38.0f;
        float gh = tgt[4 * b + 3] * 38.0f;
        int gi = (int)gx;
        int gj = (int)gy;
        float garea = gw * gh;

        // division-free argmax over anchor IoUs (first max wins)
        int best = 0;
        float binter = 0.0f, buni = 1.0f;
#pragma unroll
        for (int ai = 0; ai < NA; ai++) {
            float aw = c_bw[ai % 5] * c_sc[ai / 5];
            float ah = c_bh[ai % 5] * c_sc[ai / 5];
            float in_ = fminf(aw, gw) * fminf(ah, gh);
            float un  = aw * ah + garea - in_;
            if (ai == 0 || in_ * buni > binter * un) {
                binter = in_; buni = un; best = ai;
            }
        }
        float baw = c_bw[best % 5] * c_sc[best / 5];
        float bah = c_bh[best % 5] * c_sc[best / 5];

        const float LN2 = 0.6931471805599453f;
        BP bp;
        bp.gl = gx - 0.5f * gw;  bp.gr = gx + 0.5f * gw;
        bp.gt = gy - 0.5f * gh;  bp.gb = gy + 0.5f * gh;
        bp.garea = garea;
        bp.txt = gx - (float)gi;
        bp.tyt = gy - (float)gj;
        bp.twt = (lg2apx(gw) - lg2apx(baw)) * LN2;   // log(gw/baw)
        bp.tht = (lg2apx(gh) - lg2apx(bah)) * LN2;
        bp.sidx = gj * 38 + gi;
        bp.best = best;
        sbp = bp;
    }
    __syncthreads();
    const BP bp = sbp;

    int am = a - (a / 5) * 5;
    float aw = c_bw[am] * c_sc[a / 5];
    float ah = c_bh[am] * c_sc[a / 5];
    float lhw = __log2f(0.5f * aw);
    float lhh = __log2f(0.5f * ah);

    float acc = group_eval(X0, Y0, W0, H0, C0, 4 * v, lhw, lhh, bp);
    if (has1)
        acc += group_eval(X1, Y1, W1, H1, C1, 4 * g1, lhw, lhh, bp);

    // special-cell correction: one block per batch owns it
    if (threadIdx.x == 0 && a == bp.best) {
        int idx = bp.sidx;
        const float* p = pred + (size_t)(b * NA + a) * 5 * NHW;
        float tx = __ldg(p + idx);
        float ty = __ldg(p + idx + NHW);
        float tw = __ldg(p + idx + 2 * NHW);
        float th = __ldg(p + idx + 3 * NHW);
        float tc = __ldg(p + idx + 4 * NHW);
        int hh_ = (idx * 1725) >> 16;
        int ww_ = idx - hh_ * 38;
        CO o = cell_eval(tx, ty, tw, th, tc,
                         (float)ww_ + 0.5f, (float)hh_ + 0.5f,
                         lhw, lhh,
                         bp.gl, bp.gr, bp.gt, bp.gb, bp.garea);
        float dx = o.sx - bp.txt;
        float dy = o.sy - bp.tyt;
        float dw = tw - bp.twt;
        float dh = th - bp.tht;
        float tconf = o.inter / o.uni;
        float dc = o.pc - tconf;
        float truec = 0.5f * (dx * dx + dy * dy + dw * dw + dh * dh)
                    + 2.5f * (dc * dc);               // OBJECT_SCALE/2
        acc += truec - o.dense;
    }

    // deterministic block reduction (6 warps)
#pragma unroll
    for (int off = 16; off > 0; off >>= 1)
        acc += __shfl_down_sync(0xffffffffu, acc, off);
    if ((threadIdx.x & 31) == 0) ws[threadIdx.x >> 5] = acc;
    __syncthreads();
    if (threadIdx.x == 0) {
        float blocksum = ((ws[0] + ws[1]) + (ws[2] + ws[3])) + (ws[4] + ws[5]);
        g_part[b * NA + a] = blocksum;
        unsigned t = atomic_inc_release(&g_done);
        isLast = (t == (unsigned)(total - 1));
    }
    __syncthreads();

    // last block performs the (deterministic-order) final reduction
    if (isLast) {
        if (threadIdx.x == 0) {
            g_done = 0;          // reset for next graph replay
            __threadfence();     // single acquire-side fence, once per grid
        }
        __syncthreads();
        __shared__ double sh[NT];
        const float4* __restrict__ pp = (const float4*)g_part;
        int n4 = total >> 2;
        double s = 0.0;
        for (int i = threadIdx.x; i < n4; i += NT) {
            float4 vv = __ldcg(pp + i);   // L2 reads = coherence point
            s += ((double)vv.x + (double)vv.y) + ((double)vv.z + (double)vv.w);
        }
        sh[threadIdx.x] = s;
        __syncthreads();
        // tree over 192 = 128 + 64 fold first
        if (threadIdx.x < 64) sh[threadIdx.x] += sh[threadIdx.x + 128];
        __syncthreads();
#pragma unroll
        for (int off = 64; off > 0; off >>= 1) {
            if (threadIdx.x < off) sh[threadIdx.x] += sh[threadIdx.x + off];
            __syncthreads();
        }
        if (threadIdx.x == 0) out[0] = (float)sh[0];
    }
}

extern "C" void kernel_launch(void* const* d_in, const int* in_sizes, int n_in,
                              void* d_out, int out_size) {
    const float* pred = (const float*)d_in[0];
    const float* tgt  = (const float*)d_in[1];
    int B = in_sizes[1] / 4;
    if (B > BMAX) B = BMAX;

    dim3 grid(NA, B);
    main_kernel<<<grid, NT>>>(pred, tgt, (float*)d_out, B * NA);
}

// round 10
// speedup vs baseline: 1.4078x; 1.0220x over previous
#include <cuda_runtime.h>

#define NA   25
#define NHW  1444
#define NV   361          // NHW / 4 (float4 units per plane)
#define NT   192          // threads per block: 2 groups cover 361
#define BMAX 512

__constant__ float c_bw[5] = {1.3221f, 3.19275f, 5.05587f, 9.47112f, 11.2364f};
__constant__ float c_bh[5] = {1.73145f, 4.00944f, 8.09892f, 4.84053f, 10.0071f};
__constant__ float c_sc[5] = {0.5f, 0.75f, 1.0f, 1.25f, 1.5f};

struct BP {
    float gl, gr, gt, gb;     // gt box edges
    float garea;
    float txt, tyt, twt, tht; // coord targets at the special cell
    int   sidx, best;
};

__device__ __align__(16) float g_part[BMAX * NA];
__device__ unsigned g_done = 0;

__device__ __forceinline__ float tanhapx(float x) {
    float t;
    asm("tanh.approx.f32 %0, %1;" : "=f"(t) : "f"(x));
    return t;
}
__device__ __forceinline__ float ex2apx(float x) {
    float t;
    asm("ex2.approx.f32 %0, %1;" : "=f"(t) : "f"(x));
    return t;
}
__device__ __forceinline__ float lg2apx(float x) {
    float t;
    asm("lg2.approx.f32 %0, %1;" : "=f"(t) : "f"(x));
    return t;
}

__device__ __forceinline__ unsigned atomic_inc_release(unsigned* p) {
    unsigned old;
    asm volatile("atom.release.gpu.add.u32 %0, [%1], %2;"
                 : "=r"(old) : "l"(p), "r"(1u) : "memory");
    return old;
}

// 3-way accumulator: A = tX^2+tY^2 (x0.125), B = tw^2+th^2 (x0.5), C = pcm^2 (x0.5)
struct ACC { float A, B, C; };

// one cell, minimal instruction form
__device__ __forceinline__ void cell_hot(
    float tx, float ty, float tw, float th, float tc,
    float fw, float fh,                 // cell center coords (w+0.5, h+0.5)
    float lhw, float lhh,
    float gl, float gr, float gt, float gb, float garea,
    ACC& acc)
{
    const float L2E = 1.4426950408889634f;
    float tX = tanhapx(0.5f * tx);
    float tY = tanhapx(0.5f * ty);
    float tC = tanhapx(0.5f * tc);
    float bx = fmaf(tX, 0.5f, fw);
    float by = fmaf(tY, 0.5f, fh);
    float hw = ex2apx(fmaf(tw, L2E, lhw));     // 0.5 * aw * exp(tw)
    float hh = ex2apx(fmaf(th, L2E, lhh));
    float rx = fminf(bx + hw, gr);
    float lx = fmaxf(bx - hw, gl);
    float ry = fminf(by + hh, gb);
    float ly = fmaxf(by - hh, gt);
    float cw = fmaxf(rx - lx, 0.0f);
    float ch = fmaxf(ry - ly, 0.0f);
    float inter = cw * ch;
    float uni   = fmaf(hw * hh, 4.0f, garea) - inter;
    bool noobj  = fmaf(uni, -0.6f, inter) <= 0.0f;   // !(iou > 0.6)
    float pc  = fmaf(tC, 0.5f, 0.5f);
    float pcm = noobj ? pc : 0.0f;
    acc.A = fmaf(tX, tX, acc.A);
    acc.A = fmaf(tY, tY, acc.A);
    acc.B = fmaf(tw, tw, acc.B);
    acc.B = fmaf(th, th, acc.B);
    acc.C = fmaf(pcm, pcm, acc.C);
}

// full evaluation for the single special cell (correction path)
struct CO { float dense, inter, uni, sx, sy, pc; };
__device__ __forceinline__ CO cell_full(
    float tx, float ty, float tw, float th, float tc,
    float fw, float fh, float lhw, float lhh,
    float gl, float gr, float gt, float gb, float garea)
{
    const float L2E = 1.4426950408889634f;
    float tX = tanhapx(0.5f * tx);
    float tY = tanhapx(0.5f * ty);
    float tC = tanhapx(0.5f * tc);
    float bx = fmaf(tX, 0.5f, fw);
    float by = fmaf(tY, 0.5f, fh);
    float hw = ex2apx(fmaf(tw, L2E, lhw));
    float hh = ex2apx(fmaf(th, L2E, lhh));
    float rx = fminf(bx + hw, gr);
    float lx = fmaxf(bx - hw, gl);
    float ry = fminf(by + hh, gb);
    float ly = fmaxf(by - hh, gt);
    float cw = fmaxf(rx - lx, 0.0f);
    float ch = fmaxf(ry - ly, 0.0f);
    float inter = cw * ch;
    float uni   = fmaf(hw * hh, 4.0f, garea) - inter;
    bool noobj  = fmaf(uni, -0.6f, inter) <= 0.0f;
    float pc  = fmaf(tC, 0.5f, 0.5f);
    float pcm = noobj ? pc : 0.0f;
    CO o;
    // dense contribution exactly as hot loop (same scales applied)
    o.dense = 0.125f * fmaf(tX, tX, tY * tY)
            + 0.5f   * fmaf(tw, tw, th * th)
            + 0.5f   * (pcm * pcm);
    o.inter = inter; o.uni = uni;
    o.sx = fmaf(tX, 0.5f, 0.5f);
    o.sy = fmaf(tY, 0.5f, 0.5f);
    o.pc = pc;
    return o;
}

// process one float4 group (4 cells starting at cell index base)
__device__ __forceinline__ void group_eval(
    const float4& X, const float4& Y, const float4& W,
    const float4& H, const float4& C, int base,
    float lhw, float lhh,
    float gl, float gr, float gt, float gb, float garea,
    ACC& acc)
{
    float xa[4] = {X.x, X.y, X.z, X.w};
    float ya[4] = {Y.x, Y.y, Y.z, Y.w};
    float wa[4] = {W.x, W.y, W.z, W.w};
    float ha[4] = {H.x, H.y, H.z, H.w};
    float ca[4] = {C.x, C.y, C.z, C.w};
    // one magic divide per GROUP; per-cell predicated wrap
    int h0 = (base * 1725) >> 16;          // base / 38
    int w0 = base - h0 * 38;
    float w0f = (float)w0 + 0.5f;
    float h0f = (float)h0 + 0.5f;
#pragma unroll
    for (int k = 0; k < 4; k++) {
        float fw = w0f + (float)k;
        float fh = h0f;
        if (fw > 38.0f) { fw -= 38.0f; fh += 1.0f; }   // row wrap (at most once)
        cell_hot(xa[k], ya[k], wa[k], ha[k], ca[k],
                 fw, fh, lhw, lhh, gl, gr, gt, gb, garea, acc);
    }
}

__global__ void __launch_bounds__(NT) main_kernel(
    const float* __restrict__ pred, const float* __restrict__ tgt,
    float* __restrict__ out, int total)
{
    const int a = blockIdx.x;
    const int b = blockIdx.y;

    __shared__ BP sbp;
    __shared__ float ws[6];
    __shared__ bool isLast;

    const float4* __restrict__ p4 =
        (const float4*)(pred + (size_t)(b * NA + a) * 5 * NHW);

    const int v  = threadIdx.x;           // group0 index, always < 361
    const int g1 = v + NT;                // group1 index
    const bool has1 = (g1 < NV);          // 169 of 192 threads

    // ---- ALL loads hoisted: up to 10 independent LDG.128 before compute ----
    float4 X0 = p4[v];
    float4 Y0 = p4[v + NV];
    float4 W0 = p4[v + 2 * NV];
    float4 H0 = p4[v + 3 * NV];
    float4 C0 = p4[v + 4 * NV];
    float4 X1, Y1, W1, H1, C1;
    if (has1) {
        X1 = p4[g1];
        Y1 = p4[g1 + NV];
        W1 = p4[g1 + 2 * NV];
        H1 = p4[g1 + 3 * NV];
        C1 = p4[g1 + 4 * NV];
    }

    if (threadIdx.x == 0) {
        float gx = tgt[4 * b + 0] * 38.0f;
        float gy = tgt[4 * b + 1] * 38.0f;
        float gw = tgt[4 * b + 2] * 38.0f;
        float gh = tgt[4 * b + 3] * 38.0f;
        int gi = (int)gx;
        int gj = (int)gy;
        float garea = gw * gh;

        // division-free argmax over anchor IoUs (first max wins)
        int best = 0;
        float binter = 0.0f, buni = 1.0f;
#pragma unroll
        for (int ai = 0; ai < NA; ai++) {
            float aw = c_bw[ai % 5] * c_sc[ai / 5];
            float ah = c_bh[ai % 5] * c_sc[ai / 5];
            float in_ = fminf(aw, gw) * fminf(ah, gh);
            float un  = aw * ah + garea - in_;
            if (ai == 0 || in_ * buni > binter * un) {
                binter = in_; buni = un; best = ai;
            }
        }
        float baw = c_bw[best % 5] * c_sc[best / 5];
        float bah = c_bh[best % 5] * c_sc[best / 5];

        const float LN2 = 0.6931471805599453f;
        BP bp;
        bp.gl = gx - 0.5f * gw;  bp.gr = gx + 0.5f * gw;
        bp.gt = gy - 0.5f * gh;  bp.gb = gy + 0.5f * gh;
        bp.garea = garea;
        bp.txt = gx - (float)gi;
        bp.tyt = gy - (float)gj;
        bp.twt = (lg2apx(gw) - lg2apx(baw)) * LN2;   // log(gw/baw)
        bp.tht = (lg2apx(gh) - lg2apx(bah)) * LN2;
        bp.sidx = gj * 38 + gi;
        bp.best = best;
        sbp = bp;
    }
    __syncthreads();

    // only the 5 hot fields go to registers
    const float gl = sbp.gl, gr = sbp.gr, gt_ = sbp.gt, gb = sbp.gb;
    const float garea = sbp.garea;

    int am = a - (a / 5) * 5;
    float aw = c_bw[am] * c_sc[a / 5];
    float ah = c_bh[am] * c_sc[a / 5];
    float lhw = __log2f(0.5f * aw);
    float lhh = __log2f(0.5f * ah);

    ACC acc; acc.A = 0.0f; acc.B = 0.0f; acc.C = 0.0f;
    group_eval(X0, Y0, W0, H0, C0, 4 * v, lhw, lhh,
               gl, gr, gt_, gb, garea, acc);
    if (has1)
        group_eval(X1, Y1, W1, H1, C1, 4 * g1, lhw, lhh,
                   gl, gr, gt_, gb, garea, acc);

    float part = fmaf(0.125f, acc.A, fmaf(0.5f, acc.B, 0.5f * acc.C));

    // special-cell correction: one block per batch owns it (thread 0)
    if (threadIdx.x == 0 && a == sbp.best) {
        int idx = sbp.sidx;
        const float* p = pred + (size_t)(b * NA + a) * 5 * NHW;
        float tx = __ldg(p + idx);
        float ty = __ldg(p + idx + NHW);
        float tw = __ldg(p + idx + 2 * NHW);
        float th = __ldg(p + idx + 3 * NHW);
        float tc = __ldg(p + idx + 4 * NHW);
        int hh_ = (idx * 1725) >> 16;
        int ww_ = idx - hh_ * 38;
        CO o = cell_full(tx, ty, tw, th, tc,
                         (float)ww_ + 0.5f, (float)hh_ + 0.5f,
                         lhw, lhh, gl, gr, gt_, gb, garea);
        float dx = o.sx - sbp.txt;
        float dy = o.sy - sbp.tyt;
        float dw = tw - sbp.twt;
        float dh = th - sbp.tht;
        float tconf = o.inter / o.uni;
        float dc = o.pc - tconf;
        float truec = 0.5f * (dx * dx + dy * dy + dw * dw + dh * dh)
                    + 2.5f * (dc * dc);               // OBJECT_SCALE/2
        part += truec - o.dense;
    }

    // deterministic block reduction (6 warps)
    float accR = part;
#pragma unroll
    for (int off = 16; off > 0; off >>= 1)
        accR += __shfl_down_sync(0xffffffffu, accR, off);
    if ((threadIdx.x & 31) == 0) ws[threadIdx.x >> 5] = accR;
    __syncthreads();
    if (threadIdx.x == 0) {
        float blocksum = ((ws[0] + ws[1]) + (ws[2] + ws[3])) + (ws[4] + ws[5]);
        g_part[b * NA + a] = blocksum;
        unsigned t = atomic_inc_release(&g_done);
        isLast = (t == (unsigned)(total - 1));
    }
    __syncthreads();

    // last block performs the (deterministic-order) final reduction
    if (isLast) {
        if (threadIdx.x == 0) {
            g_done = 0;          // reset for next graph replay
            __threadfence();     // single acquire-side fence, once per grid
        }
        __syncthreads();
        __shared__ double sh[NT];
        const float4* __restrict__ pp = (const float4*)g_part;
        int n4 = total >> 2;
        double s = 0.0;
        for (int i = threadIdx.x; i < n4; i += NT) {
            float4 vv = __ldcg(pp + i);   // L2 reads = coherence point
            s += ((double)vv.x + (double)vv.y) + ((double)vv.z + (double)vv.w);
        }
        sh[threadIdx.x] = s;
        __syncthreads();
        if (threadIdx.x < 64) sh[threadIdx.x] += sh[threadIdx.x + 128];
        __syncthreads();
#pragma unroll
        for (int off = 64; off > 0; off >>= 1) {
            if (threadIdx.x < off) sh[threadIdx.x] += sh[threadIdx.x + off];
            __syncthreads();
        }
        if (threadIdx.x == 0) out[0] = (float)sh[0];
    }
}

extern "C" void kernel_launch(void* const* d_in, const int* in_sizes, int n_in,
                              void* d_out, int out_size) {
    const float* pred = (const float*)d_in[0];
    const float* tgt  = (const float*)d_in[1];
    int B = in_sizes[1] / 4;
    if (B > BMAX) B = BMAX;

    dim3 grid(NA, B);
    main_kernel<<<grid, NT>>>(pred, tgt, (float*)d_out, B * NA);
}

// round 13
// speedup vs baseline: 1.4483x; 1.0288x over previous
#include <cuda_runtime.h>

#define NA    25
#define NHW   1444
#define NV    361         // NHW / 4 (float4 units per plane)
#define PLV   1805        // float4 per (anchor) plane group of 5 fields = 5*NV
#define NT    192
#define H1ACT 169         // active threads in half-1 stage (361-192)
#define BMAX  512

__constant__ float c_bw[5] = {1.3221f, 3.19275f, 5.05587f, 9.47112f, 11.2364f};
__constant__ float c_bh[5] = {1.73145f, 4.00944f, 8.09892f, 4.84053f, 10.0071f};
__constant__ float c_sc[5] = {0.5f, 0.75f, 1.0f, 1.25f, 1.5f};

struct BP {
    float gl, gr, gt, gb, garea;
    float txt, tyt, twt, tht;
    int   sidx, best;
};

__device__ __align__(16) float g_part[BMAX * 5];
__device__ unsigned g_done = 0;

__device__ __forceinline__ float tanhapx(float x) {
    float t; asm("tanh.approx.f32 %0, %1;" : "=f"(t) : "f"(x)); return t;
}
__device__ __forceinline__ float ex2apx(float x) {
    float t; asm("ex2.approx.f32 %0, %1;" : "=f"(t) : "f"(x)); return t;
}
__device__ __forceinline__ float lg2apx(float x) {
    float t; asm("lg2.approx.f32 %0, %1;" : "=f"(t) : "f"(x)); return t;
}
__device__ __forceinline__ unsigned atomic_inc_release(unsigned* p) {
    unsigned old;
    asm volatile("atom.release.gpu.add.u32 %0, [%1], %2;"
                 : "=r"(old) : "l"(p), "r"(1u) : "memory");
    return old;
}

struct ACC { float A, B, C; };

__device__ __forceinline__ void cell_hot(
    float tx, float ty, float tw, float th, float tc,
    float fw, float fh, float lhw, float lhh,
    float gl, float gr, float gt, float gb, float garea, ACC& acc)
{
    const float L2E = 1.4426950408889634f;
    float tX = tanhapx(0.5f * tx);
    float tY = tanhapx(0.5f * ty);
    float tC = tanhapx(0.5f * tc);
    float bx = fmaf(tX, 0.5f, fw);
    float by = fmaf(tY, 0.5f, fh);
    float hw = ex2apx(fmaf(tw, L2E, lhw));
    float hh = ex2apx(fmaf(th, L2E, lhh));
    float rx = fminf(bx + hw, gr);
    float lx = fmaxf(bx - hw, gl);
    float ry = fminf(by + hh, gb);
    float ly = fmaxf(by - hh, gt);
    float cw = fmaxf(rx - lx, 0.0f);
    float ch = fmaxf(ry - ly, 0.0f);
    float inter = cw * ch;
    float uni   = fmaf(hw * hh, 4.0f, garea) - inter;
    bool noobj  = fmaf(uni, -0.6f, inter) <= 0.0f;
    float pc  = fmaf(tC, 0.5f, 0.5f);
    float pcm = noobj ? pc : 0.0f;
    acc.A = fmaf(tX, tX, acc.A);
    acc.A = fmaf(tY, tY, acc.A);
    acc.B = fmaf(tw, tw, acc.B);
    acc.B = fmaf(th, th, acc.B);
    acc.C = fmaf(pcm, pcm, acc.C);
}

struct CO { float dense, inter, uni, sx, sy, pc; };
__device__ __forceinline__ CO cell_full(
    float tx, float ty, float tw, float th, float tc,
    float fw, float fh, float lhw, float lhh,
    float gl, float gr, float gt, float gb, float garea)
{
    const float L2E = 1.4426950408889634f;
    float tX = tanhapx(0.5f * tx);
    float tY = tanhapx(0.5f * ty);
    float tC = tanhapx(0.5f * tc);
    float bx = fmaf(tX, 0.5f, fw);
    float by = fmaf(tY, 0.5f, fh);
    float hw = ex2apx(fmaf(tw, L2E, lhw));
    float hh = ex2apx(fmaf(th, L2E, lhh));
    float rx = fminf(bx + hw, gr);
    float lx = fmaxf(bx - hw, gl);
    float ry = fminf(by + hh, gb);
    float ly = fmaxf(by - hh, gt);
    float cw = fmaxf(rx - lx, 0.0f);
    float ch = fmaxf(ry - ly, 0.0f);
    float inter = cw * ch;
    float uni   = fmaf(hw * hh, 4.0f, garea) - inter;
    bool noobj  = fmaf(uni, -0.6f, inter) <= 0.0f;
    float pc  = fmaf(tC, 0.5f, 0.5f);
    float pcm = noobj ? pc : 0.0f;
    CO o;
    o.dense = 0.125f * fmaf(tX, tX, tY * tY)
            + 0.5f   * fmaf(tw, tw, th * th)
            + 0.5f   * (pcm * pcm);
    o.inter = inter; o.uni = uni;
    o.sx = fmaf(tX, 0.5f, 0.5f);
    o.sy = fmaf(tY, 0.5f, 0.5f);
    o.pc = pc;
    return o;
}

__device__ __forceinline__ void load_grp(float4 buf[5],
    const float4* __restrict__ p4, int goff)
{
    buf[0] = p4[goff];
    buf[1] = p4[goff + NV];
    buf[2] = p4[goff + 2 * NV];
    buf[3] = p4[goff + 3 * NV];
    buf[4] = p4[goff + 4 * NV];
}

__device__ __forceinline__ void comp_grp(const float4 buf[5], int base,
    float lhw, float lhh,
    float gl, float gr, float gt, float gb, float garea, ACC& acc)
{
    float xa[4] = {buf[0].x, buf[0].y, buf[0].z, buf[0].w};
    float ya[4] = {buf[1].x, buf[1].y, buf[1].z, buf[1].w};
    float wa[4] = {buf[2].x, buf[2].y, buf[2].z, buf[2].w};
    float ha[4] = {buf[3].x, buf[3].y, buf[3].z, buf[3].w};
    float ca[4] = {buf[4].x, buf[4].y, buf[4].z, buf[4].w};
    int h0 = (base * 1725) >> 16;
    int w0 = base - h0 * 38;
    float w0f = (float)w0 + 0.5f;
    float h0f = (float)h0 + 0.5f;
#pragma unroll
    for (int k = 0; k < 4; k++) {
        float fw = w0f + (float)k;
        float fh = h0f;
        if (fw > 38.0f) { fw -= 38.0f; fh += 1.0f; }
        cell_hot(xa[k], ya[k], wa[k], ha[k], ca[k],
                 fw, fh, lhw, lhh, gl, gr, gt, gb, garea, acc);
    }
}

__global__ void __launch_bounds__(NT) main_kernel(
    const float* __restrict__ pred, const float* __restrict__ tgt,
    float* __restrict__ out, int total)
{
    const int g = blockIdx.x;                 // anchor group: a = 5g..5g+4
    const int b = blockIdx.y;

    __shared__ BP sbp;
    __shared__ float ws[6];
    __shared__ bool isLast;

    // base of anchor plane 5g for this batch; planes j are +j*PLV float4
    const float4* __restrict__ p4 =
        (const float4*)(pred + (size_t)(b * NA + g * 5) * 5 * NHW);

    const int v = threadIdx.x;
    const bool act1 = (v < H1ACT);

    // buffers (double-buffered pipeline)
    float4 bufA[5], bufB[5];

    // prefetch stage 0 (anchor 0, half 0) BEFORE prologue
    load_grp(bufA, p4, v);

    if (threadIdx.x == 0) {
        float gx = tgt[4 * b + 0] * 38.0f;
        float gy = tgt[4 * b + 1] * 38.0f;
        float gw = tgt[4 * b + 2] * 38.0f;
        float gh = tgt[4 * b + 3] * 38.0f;
        int gi = (int)gx;
        int gj = (int)gy;
        float garea = gw * gh;

        int best = 0;
        float binter = 0.0f, buni = 1.0f;
#pragma unroll
        for (int ai = 0; ai < NA; ai++) {
            float aw = c_bw[ai % 5] * c_sc[ai / 5];
            float ah = c_bh[ai % 5] * c_sc[ai / 5];
            float in_ = fminf(aw, gw) * fminf(ah, gh);
            float un  = aw * ah + garea - in_;
            if (ai == 0 || in_ * buni > binter * un) {
                binter = in_; buni = un; best = ai;
            }
        }
        float baw = c_bw[best % 5] * c_sc[best / 5];
        float bah = c_bh[best % 5] * c_sc[best / 5];

        const float LN2 = 0.6931471805599453f;
        BP bp;
        bp.gl = gx - 0.5f * gw;  bp.gr = gx + 0.5f * gw;
        bp.gt = gy - 0.5f * gh;  bp.gb = gy + 0.5f * gh;
        bp.garea = garea;
        bp.txt = gx - (float)gi;
        bp.tyt = gy - (float)gj;
        bp.twt = (lg2apx(gw) - lg2apx(baw)) * LN2;
        bp.tht = (lg2apx(gh) - lg2apx(bah)) * LN2;
        bp.sidx = gj * 38 + gi;
        bp.best = best;
        sbp = bp;
    }
    __syncthreads();

    const float gl = sbp.gl, gr = sbp.gr, gt_ = sbp.gt, gb = sbp.gb;
    const float garea = sbp.garea;
    const float sc = c_sc[g];

    ACC acc; acc.A = 0.0f; acc.B = 0.0f; acc.C = 0.0f;

    // 10-stage pipeline: anchors j=0..4, halves 0/1, double-buffered.
    // While computing one stage, the next stage's 5 LDG.128 are in flight.
#pragma unroll
    for (int j = 0; j < 5; j++) {
        const float4* pj = p4 + j * PLV;
        float lhw = __log2f(0.5f * c_bw[j] * sc);
        float lhh = __log2f(0.5f * c_bh[j] * sc);

        // prefetch (j, half1)
        if (act1) load_grp(bufB, pj, NT + v);
        // compute (j, half0)
        comp_grp(bufA, 4 * v, lhw, lhh, gl, gr, gt_, gb, garea, acc);
        // prefetch (j+1, half0)
        if (j < 4) load_grp(bufA, pj + PLV, v);
        // compute (j, half1)
        if (act1) comp_grp(bufB, 4 * (NT + v), lhw, lhh,
                           gl, gr, gt_, gb, garea, acc);
    }

    float part = fmaf(0.125f, acc.A, fmaf(0.5f, acc.B, 0.5f * acc.C));

    // special-cell correction: block owning the best anchor (one per batch)
    if (threadIdx.x == 0 && sbp.best >= g * 5 && sbp.best < g * 5 + 5) {
        int j = sbp.best - g * 5;
        int idx = sbp.sidx;
        const float* p = (const float*)(p4 + j * PLV);
        float tx = __ldg(p + idx);
        float ty = __ldg(p + idx + NHW);
        float tw = __ldg(p + idx + 2 * NHW);
        float th = __ldg(p + idx + 3 * NHW);
        float tc = __ldg(p + idx + 4 * NHW);
        float lhw = __log2f(0.5f * c_bw[j] * sc);
        float lhh = __log2f(0.5f * c_bh[j] * sc);
        int hh_ = (idx * 1725) >> 16;
        int ww_ = idx - hh_ * 38;
        CO o = cell_full(tx, ty, tw, th, tc,
                         (float)ww_ + 0.5f, (float)hh_ + 0.5f,
                         lhw, lhh, gl, gr, gt_, gb, garea);
        float dx = o.sx - sbp.txt;
        float dy = o.sy - sbp.tyt;
        float dw = tw - sbp.twt;
        float dh = th - sbp.tht;
        float tconf = o.inter / o.uni;
        float dc = o.pc - tconf;
        float truec = 0.5f * (dx * dx + dy * dy + dw * dw + dh * dh)
                    + 2.5f * (dc * dc);
        part += truec - o.dense;
    }

    // deterministic block reduction (6 warps)
    float accR = part;
#pragma unroll
    for (int off = 16; off > 0; off >>= 1)
        accR += __shfl_down_sync(0xffffffffu, accR, off);
    if ((threadIdx.x & 31) == 0) ws[threadIdx.x >> 5] = accR;
    __syncthreads();
    if (threadIdx.x == 0) {
        float blocksum = ((ws[0] + ws[1]) + (ws[2] + ws[3])) + (ws[4] + ws[5]);
        g_part[b * 5 + g] = blocksum;
        unsigned t = atomic_inc_release(&g_done);
        isLast = (t == (unsigned)(total - 1));
    }
    __syncthreads();

    if (isLast) {
        if (threadIdx.x == 0) {
            g_done = 0;
            __threadfence();
        }
        __syncthreads();
        __shared__ double sh[NT];
        const float4* __restrict__ pp = (const float4*)g_part;
        int n4 = total >> 2;
        double s = 0.0;
        for (int i = threadIdx.x; i < n4; i += NT) {
            float4 vv = __ldcg(pp + i);
            s += ((double)vv.x + (double)vv.y) + ((double)vv.z + (double)vv.w);
        }
        sh[threadIdx.x] = s;
        __syncthreads();
        if (threadIdx.x < 64) sh[threadIdx.x] += sh[threadIdx.x + 128];
        __syncthreads();
#pragma unroll
        for (int off = 64; off > 0; off >>= 1) {
            if (threadIdx.x < off) sh[threadIdx.x] += sh[threadIdx.x + off];
            __syncthreads();
        }
        if (threadIdx.x == 0) out[0] = (float)sh[0];
    }
}

extern "C" void kernel_launch(void* const* d_in, const int* in_sizes, int n_in,
                              void* d_out, int out_size) {
    const float* pred = (const float*)d_in[0];
    const float* tgt  = (const float*)d_in[1];
    int B = in_sizes[1] / 4;
    if (B > BMAX) B = BMAX;

    dim3 grid(5, B);
    main_kernel<<<grid, NT>>>(pred, tgt, (float*)d_out, B * 5);
}

// round 15
// speedup vs baseline: 1.5801x; 1.0910x over previous
#include <cuda_runtime.h>

#define NA    25
#define NHW   1444
#define NV    361         // float4 per field-plane
#define PLV   1805        // float4 per anchor (5 fields)
#define NT    192
#define H0CNT 181         // groups in half 0
#define H1CNT 180         // groups in half 1
#define FSTR  182         // smem field stride (float4), padded
#define STG4  (5 * FSTR)  // float4 per smem stage buffer
#define BMAX  512

__constant__ float c_bw[5] = {1.3221f, 3.19275f, 5.05587f, 9.47112f, 11.2364f};
__constant__ float c_bh[5] = {1.73145f, 4.00944f, 8.09892f, 4.84053f, 10.0071f};
__constant__ float c_sc[5] = {0.5f, 0.75f, 1.0f, 1.25f, 1.5f};

struct BP {
    float gl, gr, gt, gb, garea;
    float txt, tyt, twt, tht;
    int   sidx, best;
};

__device__ __align__(16) float g_part[BMAX * 5];
__device__ unsigned g_done = 0;

__device__ __forceinline__ float tanhapx(float x) {
    float t; asm("tanh.approx.f32 %0, %1;" : "=f"(t) : "f"(x)); return t;
}
__device__ __forceinline__ float ex2apx(float x) {
    float t; asm("ex2.approx.f32 %0, %1;" : "=f"(t) : "f"(x)); return t;
}
__device__ __forceinline__ float lg2apx(float x) {
    float t; asm("lg2.approx.f32 %0, %1;" : "=f"(t) : "f"(x)); return t;
}
__device__ __forceinline__ unsigned atomic_inc_release(unsigned* p) {
    unsigned old;
    asm volatile("atom.release.gpu.add.u32 %0, [%1], %2;"
                 : "=r"(old) : "l"(p), "r"(1u) : "memory");
    return old;
}

__device__ __forceinline__ void cp_async16(void* sdst, const void* gsrc) {
    unsigned saddr = (unsigned)__cvta_generic_to_shared(sdst);
    asm volatile("cp.async.cg.shared.global [%0], [%1], 16;"
                 :: "r"(saddr), "l"(gsrc));
}
__device__ __forceinline__ void cp_commit() {
    asm volatile("cp.async.commit_group;");
}
template<int N> __device__ __forceinline__ void cp_wait() {
    asm volatile("cp.async.wait_group %0;" :: "n"(N));
}

struct ACC { float A, B, C; };

__device__ __forceinline__ void cell_hot(
    float tx, float ty, float tw, float th, float tc,
    float fw, float fh, float lhw, float lhh,
    float gl, float gr, float gt, float gb, float garea, ACC& acc)
{
    const float L2E = 1.4426950408889634f;
    float tX = tanhapx(0.5f * tx);
    float tY = tanhapx(0.5f * ty);
    float tC = tanhapx(0.5f * tc);
    float bx = fmaf(tX, 0.5f, fw);
    float by = fmaf(tY, 0.5f, fh);
    float hw = ex2apx(fmaf(tw, L2E, lhw));
    float hh = ex2apx(fmaf(th, L2E, lhh));
    float rx = fminf(bx + hw, gr);
    float lx = fmaxf(bx - hw, gl);
    float ry = fminf(by + hh, gb);
    float ly = fmaxf(by - hh, gt);
    float cw = fmaxf(rx - lx, 0.0f);
    float ch = fmaxf(ry - ly, 0.0f);
    float inter = cw * ch;
    float uni   = fmaf(hw * hh, 4.0f, garea) - inter;
    bool noobj  = fmaf(uni, -0.6f, inter) <= 0.0f;
    float pc  = fmaf(tC, 0.5f, 0.5f);
    float pcm = noobj ? pc : 0.0f;
    acc.A = fmaf(tX, tX, acc.A);
    acc.A = fmaf(tY, tY, acc.A);
    acc.B = fmaf(tw, tw, acc.B);
    acc.B = fmaf(th, th, acc.B);
    acc.C = fmaf(pcm, pcm, acc.C);
}

struct CO { float dense, inter, uni, sx, sy, pc; };
__device__ __forceinline__ CO cell_full(
    float tx, float ty, float tw, float th, float tc,
    float fw, float fh, float lhw, float lhh,
    float gl, float gr, float gt, float gb, float garea)
{
    const float L2E = 1.4426950408889634f;
    float tX = tanhapx(0.5f * tx);
    float tY = tanhapx(0.5f * ty);
    float tC = tanhapx(0.5f * tc);
    float bx = fmaf(tX, 0.5f, fw);
    float by = fmaf(tY, 0.5f, fh);
    float hw = ex2apx(fmaf(tw, L2E, lhw));
    float hh = ex2apx(fmaf(th, L2E, lhh));
    float rx = fminf(bx + hw, gr);
    float lx = fmaxf(bx - hw, gl);
    float ry = fminf(by + hh, gb);
    float ly = fmaxf(by - hh, gt);
    float cw = fmaxf(rx - lx, 0.0f);
    float ch = fmaxf(ry - ly, 0.0f);
    float inter = cw * ch;
    float uni   = fmaf(hw * hh, 4.0f, garea) - inter;
    bool noobj  = fmaf(uni, -0.6f, inter) <= 0.0f;
    float pc  = fmaf(tC, 0.5f, 0.5f);
    float pcm = noobj ? pc : 0.0f;
    CO o;
    o.dense = 0.125f * fmaf(tX, tX, tY * tY)
            + 0.5f   * fmaf(tw, tw, th * th)
            + 0.5f   * (pcm * pcm);
    o.inter = inter; o.uni = uni;
    o.sx = fmaf(tX, 0.5f, 0.5f);
    o.sy = fmaf(tY, 0.5f, 0.5f);
    o.pc = pc;
    return o;
}

// issue cp.async for one stage (anchor j, half h): 5 strided field segments
__device__ __forceinline__ void stage_load(
    float4* sdst, const float4* __restrict__ p4, int j, int h, int tid)
{
    const float4* gsrc = p4 + j * PLV + h * H0CNT;
    const int cnt = h ? H1CNT : H0CNT;
    if (tid < cnt) {
#pragma unroll
        for (int f = 0; f < 5; f++)
            cp_async16(sdst + f * FSTR + tid, gsrc + f * NV + tid);
    }
}

__global__ void __launch_bounds__(NT) main_kernel(
    const float* __restrict__ pred, const float* __restrict__ tgt,
    float* __restrict__ out, int total)
{
    const int g = blockIdx.x;                 // anchor group: a = 5g..5g+4
    const int b = blockIdx.y;

    __shared__ __align__(16) float4 sbuf[2][STG4];   // 29120 B
    __shared__ BP sbp;
    __shared__ float ws[6];
    __shared__ bool isLast;

    const float4* __restrict__ p4 =
        (const float4*)(pred + (size_t)(b * NA + g * 5) * 5 * NHW);

    const int v = threadIdx.x;

    // prefetch stage 0 before the prologue
    stage_load(sbuf[0], p4, 0, 0, v);
    cp_commit();

    if (threadIdx.x == 0) {
        float gx = tgt[4 * b + 0] * 38.0f;
        float gy = tgt[4 * b + 1] * 38.0f;
        float gw = tgt[4 * b + 2] * 38.0f;
        float gh = tgt[4 * b + 3] * 38.0f;
        int gi = (int)gx;
        int gj = (int)gy;
        float garea = gw * gh;

        int best = 0;
        float binter = 0.0f, buni = 1.0f;
#pragma unroll
        for (int ai = 0; ai < NA; ai++) {
            float aw = c_bw[ai % 5] * c_sc[ai / 5];
            float ah = c_bh[ai % 5] * c_sc[ai / 5];
            float in_ = fminf(aw, gw) * fminf(ah, gh);
            float un  = aw * ah + garea - in_;
            if (ai == 0 || in_ * buni > binter * un) {
                binter = in_; buni = un; best = ai;
            }
        }
        float baw = c_bw[best % 5] * c_sc[best / 5];
        float bah = c_bh[best % 5] * c_sc[best / 5];

        const float LN2 = 0.6931471805599453f;
        BP bp;
        bp.gl = gx - 0.5f * gw;  bp.gr = gx + 0.5f * gw;
        bp.gt = gy - 0.5f * gh;  bp.gb = gy + 0.5f * gh;
        bp.garea = garea;
        bp.txt = gx - (float)gi;
        bp.tyt = gy - (float)gj;
        bp.twt = (lg2apx(gw) - lg2apx(baw)) * LN2;
        bp.tht = (lg2apx(gh) - lg2apx(bah)) * LN2;
        bp.sidx = gj * 38 + gi;
        bp.best = best;
        sbp = bp;
    }
    __syncthreads();

    const float gl = sbp.gl, gr = sbp.gr, gt_ = sbp.gt, gb = sbp.gb;
    const float garea = sbp.garea;
    const float sc = c_sc[g];

    ACC acc; acc.A = 0.0f; acc.B = 0.0f; acc.C = 0.0f;

    // 10-stage cp.async pipeline: stage s = (anchor s/2, half s&1)
#pragma unroll
    for (int s = 0; s < 10; s++) {
        const int cur = s & 1;          // sbuf index of current stage
        // issue next stage's copy into the other buffer (safe: that buffer's
        // previous compute finished at the trailing barrier of iter s-1)
        if (s < 9) {
            stage_load(sbuf[cur ^ 1], p4, (s + 1) >> 1, (s + 1) & 1, v);
            cp_commit();
            cp_wait<1>();               // current stage complete
        } else {
            cp_wait<0>();
        }
        __syncthreads();

        const int j = s >> 1, h = s & 1;
        const int cnt = h ? H1CNT : H0CNT;
        const float lhw = __log2f(0.5f * c_bw[j] * sc);
        const float lhh = __log2f(0.5f * c_bh[j] * sc);

        if (v < cnt) {
            const float4* sb = sbuf[cur];
            float4 X = sb[v];
            float4 Y = sb[v + FSTR];
            float4 W = sb[v + 2 * FSTR];
            float4 H = sb[v + 3 * FSTR];
            float4 C = sb[v + 4 * FSTR];
            float xa[4] = {X.x, X.y, X.z, X.w};
            float ya[4] = {Y.x, Y.y, Y.z, Y.w};
            float wa[4] = {W.x, W.y, W.z, W.w};
            float ha[4] = {H.x, H.y, H.z, H.w};
            float ca[4] = {C.x, C.y, C.z, C.w};
            int base = 4 * (h * H0CNT + v);
            int h0 = (base * 1725) >> 16;
            int w0 = base - h0 * 38;
            float w0f = (float)w0 + 0.5f;
            float h0f = (float)h0 + 0.5f;
#pragma unroll
            for (int k = 0; k < 4; k++) {
                float fw = w0f + (float)k;
                float fh = h0f;
                if (fw > 38.0f) { fw -= 38.0f; fh += 1.0f; }
                cell_hot(xa[k], ya[k], wa[k], ha[k], ca[k],
                         fw, fh, lhw, lhh, gl, gr, gt_, gb, garea, acc);
            }
        }
        __syncthreads();   // stage consumed; buffer may be overwritten
    }

    float part = fmaf(0.125f, acc.A, fmaf(0.5f, acc.B, 0.5f * acc.C));

    // special-cell correction (one block per batch owns it)
    if (threadIdx.x == 0 && sbp.best >= g * 5 && sbp.best < g * 5 + 5) {
        int j = sbp.best - g * 5;
        int idx = sbp.sidx;
        const float* p = (const float*)(p4 + j * PLV);
        float tx = __ldg(p + idx);
        float ty = __ldg(p + idx + NHW);
        float tw = __ldg(p + idx + 2 * NHW);
        float th = __ldg(p + idx + 3 * NHW);
        float tc = __ldg(p + idx + 4 * NHW);
        float lhw = __log2f(0.5f * c_bw[j] * sc);
        float lhh = __log2f(0.5f * c_bh[j] * sc);
        int hh_ = (idx * 1725) >> 16;
        int ww_ = idx - hh_ * 38;
        CO o = cell_full(tx, ty, tw, th, tc,
                         (float)ww_ + 0.5f, (float)hh_ + 0.5f,
                         lhw, lhh, gl, gr, gt_, gb, garea);
        float dx = o.sx - sbp.txt;
        float dy = o.sy - sbp.tyt;
        float dw = tw - sbp.twt;
        float dh = th - sbp.tht;
        float tconf = o.inter / o.uni;
        float dc = o.pc - tconf;
        float truec = 0.5f * (dx * dx + dy * dy + dw * dw + dh * dh)
                    + 2.5f * (dc * dc);
        part += truec - o.dense;
    }

    // deterministic block reduction (6 warps)
    float accR = part;
#pragma unroll
    for (int off = 16; off > 0; off >>= 1)
        accR += __shfl_down_sync(0xffffffffu, accR, off);
    if ((threadIdx.x & 31) == 0) ws[threadIdx.x >> 5] = accR;
    __syncthreads();
    if (threadIdx.x == 0) {
        float blocksum = ((ws[0] + ws[1]) + (ws[2] + ws[3])) + (ws[4] + ws[5]);
        g_part[b * 5 + g] = blocksum;
        unsigned t = atomic_inc_release(&g_done);
        isLast = (t == (unsigned)(total - 1));
    }
    __syncthreads();

    if (isLast) {
        if (threadIdx.x == 0) {
            g_done = 0;
            __threadfence();
        }
        __syncthreads();
        __shared__ double sh[NT];
        const float4* __restrict__ pp = (const float4*)g_part;
        int n4 = total >> 2;
        double s = 0.0;
        for (int i = threadIdx.x; i < n4; i += NT) {
            float4 vv = __ldcg(pp + i);
            s += ((double)vv.x + (double)vv.y) + ((double)vv.z + (double)vv.w);
        }
        sh[threadIdx.x] = s;
        __syncthreads();
        if (threadIdx.x < 64) sh[threadIdx.x] += sh[threadIdx.x + 128];
        __syncthreads();
#pragma unroll
        for (int off = 64; off > 0; off >>= 1) {
            if (threadIdx.x < off) sh[threadIdx.x] += sh[threadIdx.x + off];
            __syncthreads();
        }
        if (threadIdx.x == 0) out[0] = (float)sh[0];
    }
}

extern "C" void kernel_launch(void* const* d_in, const int* in_sizes, int n_in,
                              void* d_out, int out_size) {
    const float* pred = (const float*)d_in[0];
    const float* tgt  = (const float*)d_in[1];
    int B = in_sizes[1] / 4;
    if (B > BMAX) B = BMAX;

    dim3 grid(5, B);
    main_kernel<<<grid, NT>>>(pred, tgt, (float*)d_out, B * 5);
}

// round 16
// speedup vs baseline: 1.5831x; 1.0019x over previous
#include <cuda_runtime.h>

#define NA    25
#define NHW   1444
#define NV    361         // float4 per field-plane
#define PLV   1805        // float4 per anchor (5 fields)
#define NT    192
#define H0CNT 181         // groups in half 0
#define H1CNT 180         // groups in half 1
#define FSTR  182         // smem field stride (float4), padded
#define STG4  (5 * FSTR)  // float4 per smem stage buffer
#define BMAX  512

__constant__ float c_bw[5] = {1.3221f, 3.19275f, 5.05587f, 9.47112f, 11.2364f};
__constant__ float c_bh[5] = {1.73145f, 4.00944f, 8.09892f, 4.84053f, 10.0071f};
__constant__ float c_sc[5] = {0.5f, 0.75f, 1.0f, 1.25f, 1.5f};

struct BP {
    float gl, gr, gt, gb, garea;
    float txt, tyt, twt, tht;
    int   sidx, best;
};

__device__ __align__(16) float g_part[BMAX * 5];
__device__ unsigned g_done = 0;

__device__ __forceinline__ float tanhapx(float x) {
    float t; asm("tanh.approx.f32 %0, %1;" : "=f"(t) : "f"(x)); return t;
}
__device__ __forceinline__ float ex2apx(float x) {
    float t; asm("ex2.approx.f32 %0, %1;" : "=f"(t) : "f"(x)); return t;
}
__device__ __forceinline__ float lg2apx(float x) {
    float t; asm("lg2.approx.f32 %0, %1;" : "=f"(t) : "f"(x)); return t;
}
__device__ __forceinline__ unsigned atomic_inc_release(unsigned* p) {
    unsigned old;
    asm volatile("atom.release.gpu.add.u32 %0, [%1], %2;"
                 : "=r"(old) : "l"(p), "r"(1u) : "memory");
    return old;
}

__device__ __forceinline__ void cp_async16(void* sdst, const void* gsrc) {
    unsigned saddr = (unsigned)__cvta_generic_to_shared(sdst);
    asm volatile("cp.async.cg.shared.global [%0], [%1], 16;"
                 :: "r"(saddr), "l"(gsrc));
}
__device__ __forceinline__ void cp_commit() {
    asm volatile("cp.async.commit_group;");
}
template<int N> __device__ __forceinline__ void cp_wait() {
    asm volatile("cp.async.wait_group %0;" :: "n"(N));
}

struct ACC { float A, B, C; };

__device__ __forceinline__ void cell_hot(
    float tx, float ty, float tw, float th, float tc,
    float fw, float fh, float lhw, float lhh,
    float gl, float gr, float gt, float gb, float garea, ACC& acc)
{
    const float L2E = 1.4426950408889634f;
    float tX = tanhapx(0.5f * tx);
    float tY = tanhapx(0.5f * ty);
    float tC = tanhapx(0.5f * tc);
    float bx = fmaf(tX, 0.5f, fw);
    float by = fmaf(tY, 0.5f, fh);
    float hw = ex2apx(fmaf(tw, L2E, lhw));
    float hh = ex2apx(fmaf(th, L2E, lhh));
    float rx = fminf(bx + hw, gr);
    float lx = fmaxf(bx - hw, gl);
    float ry = fminf(by + hh, gb);
    float ly = fmaxf(by - hh, gt);
    float cw = fmaxf(rx - lx, 0.0f);
    float ch = fmaxf(ry - ly, 0.0f);
    float inter = cw * ch;
    float uni   = fmaf(hw * hh, 4.0f, garea) - inter;
    bool noobj  = fmaf(uni, -0.6f, inter) <= 0.0f;
    float pc  = fmaf(tC, 0.5f, 0.5f);
    float pcm = noobj ? pc : 0.0f;
    acc.A = fmaf(tX, tX, acc.A);
    acc.A = fmaf(tY, tY, acc.A);
    acc.B = fmaf(tw, tw, acc.B);
    acc.B = fmaf(th, th, acc.B);
    acc.C = fmaf(pcm, pcm, acc.C);
}

struct CO { float dense, inter, uni, sx, sy, pc; };
__device__ __forceinline__ CO cell_full(
    float tx, float ty, float tw, float th, float tc,
    float fw, float fh, float lhw, float lhh,
    float gl, float gr, float gt, float gb, float garea)
{
    const float L2E = 1.4426950408889634f;
    float tX = tanhapx(0.5f * tx);
    float tY = tanhapx(0.5f * ty);
    float tC = tanhapx(0.5f * tc);
    float bx = fmaf(tX, 0.5f, fw);
    float by = fmaf(tY, 0.5f, fh);
    float hw = ex2apx(fmaf(tw, L2E, lhw));
    float hh = ex2apx(fmaf(th, L2E, lhh));
    float rx = fminf(bx + hw, gr);
    float lx = fmaxf(bx - hw, gl);
    float ry = fminf(by + hh, gb);
    float ly = fmaxf(by - hh, gt);
    float cw = fmaxf(rx - lx, 0.0f);
    float ch = fmaxf(ry - ly, 0.0f);
    float inter = cw * ch;
    float uni   = fmaf(hw * hh, 4.0f, garea) - inter;
    bool noobj  = fmaf(uni, -0.6f, inter) <= 0.0f;
    float pc  = fmaf(tC, 0.5f, 0.5f);
    float pcm = noobj ? pc : 0.0f;
    CO o;
    o.dense = 0.125f * fmaf(tX, tX, tY * tY)
            + 0.5f   * fmaf(tw, tw, th * th)
            + 0.5f   * (pcm * pcm);
    o.inter = inter; o.uni = uni;
    o.sx = fmaf(tX, 0.5f, 0.5f);
    o.sy = fmaf(tY, 0.5f, 0.5f);
    o.pc = pc;
    return o;
}

// issue cp.async for one stage (anchor j, half h): 5 strided field segments
__device__ __forceinline__ void stage_load(
    float4* sdst, const float4* __restrict__ p4, int j, int h, int tid)
{
    const float4* gsrc = p4 + j * PLV + h * H0CNT;
    const int cnt = h ? H1CNT : H0CNT;
    if (tid < cnt) {
#pragma unroll
        for (int f = 0; f < 5; f++)
            cp_async16(sdst + f * FSTR + tid, gsrc + f * NV + tid);
    }
}

__global__ void __launch_bounds__(NT) main_kernel(
    const float* __restrict__ pred, const float* __restrict__ tgt,
    float* __restrict__ out, int total)
{
    const int g = blockIdx.x;                 // anchor group: a = 5g..5g+4
    const int b = blockIdx.y;

    __shared__ __align__(16) float4 sbuf[3][STG4];   // 43,680 B (triple buffer)
    __shared__ BP sbp;
    __shared__ float ws[6];
    __shared__ bool isLast;

    const float4* __restrict__ p4 =
        (const float4*)(pred + (size_t)(b * NA + g * 5) * 5 * NHW);

    const int v = threadIdx.x;

    // prefetch stages 0 and 1 before the prologue (2 groups in flight)
    stage_load(sbuf[0], p4, 0, 0, v);
    cp_commit();
    stage_load(sbuf[1], p4, 0, 1, v);
    cp_commit();

    if (threadIdx.x == 0) {
        float gx = tgt[4 * b + 0] * 38.0f;
        float gy = tgt[4 * b + 1] * 38.0f;
        float gw = tgt[4 * b + 2] * 38.0f;
        float gh = tgt[4 * b + 3] * 38.0f;
        int gi = (int)gx;
        int gj = (int)gy;
        float garea = gw * gh;

        int best = 0;
        float binter = 0.0f, buni = 1.0f;
#pragma unroll
        for (int ai = 0; ai < NA; ai++) {
            float aw = c_bw[ai % 5] * c_sc[ai / 5];
            float ah = c_bh[ai % 5] * c_sc[ai / 5];
            float in_ = fminf(aw, gw) * fminf(ah, gh);
            float un  = aw * ah + garea - in_;
            if (ai == 0 || in_ * buni > binter * un) {
                binter = in_; buni = un; best = ai;
            }
        }
        float baw = c_bw[best % 5] * c_sc[best / 5];
        float bah = c_bh[best % 5] * c_sc[best / 5];

        const float LN2 = 0.6931471805599453f;
        BP bp;
        bp.gl = gx - 0.5f * gw;  bp.gr = gx + 0.5f * gw;
        bp.gt = gy - 0.5f * gh;  bp.gb = gy + 0.5f * gh;
        bp.garea = garea;
        bp.txt = gx - (float)gi;
        bp.tyt = gy - (float)gj;
        bp.twt = (lg2apx(gw) - lg2apx(baw)) * LN2;
        bp.tht = (lg2apx(gh) - lg2apx(bah)) * LN2;
        bp.sidx = gj * 38 + gi;
        bp.best = best;
        sbp = bp;
    }
    __syncthreads();

    const float gl = sbp.gl, gr = sbp.gr, gt_ = sbp.gt, gb = sbp.gb;
    const float garea = sbp.garea;
    const float sc = c_sc[g];

    ACC acc; acc.A = 0.0f; acc.B = 0.0f; acc.C = 0.0f;

    // 10-stage pipeline, triple-buffered, 2 stages in flight.
    // At stage s: issue s+2 into sbuf[(s+2)%3], wait for s, compute sbuf[s%3].
    // Overwrite safety: load for s+2 targets the buffer computed at s-1;
    // the trailing barrier of stage s-1 orders that compute before this issue.
#pragma unroll
    for (int s = 0; s < 10; s++) {
        const int cur = s % 3;
        if (s < 8) {
            stage_load(sbuf[(s + 2) % 3], p4, (s + 2) >> 1, (s + 2) & 1, v);
            cp_commit();
            cp_wait<2>();               // stage s complete (s+1, s+2 in flight)
        } else if (s == 8) {
            cp_wait<1>();
        } else {
            cp_wait<0>();
        }
        __syncthreads();

        const int j = s >> 1, h = s & 1;
        const int cnt = h ? H1CNT : H0CNT;
        const float lhw = __log2f(0.5f * c_bw[j] * sc);
        const float lhh = __log2f(0.5f * c_bh[j] * sc);

        if (v < cnt) {
            const float4* sb = sbuf[cur];
            float4 X = sb[v];
            float4 Y = sb[v + FSTR];
            float4 W = sb[v + 2 * FSTR];
            float4 H = sb[v + 3 * FSTR];
            float4 C = sb[v + 4 * FSTR];
            float xa[4] = {X.x, X.y, X.z, X.w};
            float ya[4] = {Y.x, Y.y, Y.z, Y.w};
            float wa[4] = {W.x, W.y, W.z, W.w};
            float ha[4] = {H.x, H.y, H.z, H.w};
            float ca[4] = {C.x, C.y, C.z, C.w};
            int base = 4 * (h * H0CNT + v);
            int h0 = (base * 1725) >> 16;
            int w0 = base - h0 * 38;
            float w0f = (float)w0 + 0.5f;
            float h0f = (float)h0 + 0.5f;
#pragma unroll
            for (int k = 0; k < 4; k++) {
                float fw = w0f + (float)k;
                float fh = h0f;
                if (fw > 38.0f) { fw -= 38.0f; fh += 1.0f; }
                cell_hot(xa[k], ya[k], wa[k], ha[k], ca[k],
                         fw, fh, lhw, lhh, gl, gr, gt_, gb, garea, acc);
            }
        }
        __syncthreads();   // stage consumed; buffer may be overwritten at s+1
    }

    float part = fmaf(0.125f, acc.A, fmaf(0.5f, acc.B, 0.5f * acc.C));

    // special-cell correction (one block per batch owns it)
    if (threadIdx.x == 0 && sbp.best >= g * 5 && sbp.best < g * 5 + 5) {
        int j = sbp.best - g * 5;
        int idx = sbp.sidx;
        const float* p = (const float*)(p4 + j * PLV);
        float tx = __ldg(p + idx);
        float ty = __ldg(p + idx + NHW);
        float tw = __ldg(p + idx + 2 * NHW);
        float th = __ldg(p + idx + 3 * NHW);
        float tc = __ldg(p + idx + 4 * NHW);
        float lhw = __log2f(0.5f * c_bw[j] * sc);
        float lhh = __log2f(0.5f * c_bh[j] * sc);
        int hh_ = (idx * 1725) >> 16;
        int ww_ = idx - hh_ * 38;
        CO o = cell_full(tx, ty, tw, th, tc,
                         (float)ww_ + 0.5f, (float)hh_ + 0.5f,
                         lhw, lhh, gl, gr, gt_, gb, garea);
        float dx = o.sx - sbp.txt;
        float dy = o.sy - sbp.tyt;
        float dw = tw - sbp.twt;
        float dh = th - sbp.tht;
        float tconf = o.inter / o.uni;
        float dc = o.pc - tconf;
        float truec = 0.5f * (dx * dx + dy * dy + dw * dw + dh * dh)
                    + 2.5f * (dc * dc);
        part += truec - o.dense;
    }

    // deterministic block reduction (6 warps)
    float accR = part;
#pragma unroll
    for (int off = 16; off > 0; off >>= 1)
        accR += __shfl_down_sync(0xffffffffu, accR, off);
    if ((threadIdx.x & 31) == 0) ws[threadIdx.x >> 5] = accR;
    __syncthreads();
    if (threadIdx.x == 0) {
        float blocksum = ((ws[0] + ws[1]) + (ws[2] + ws[3])) + (ws[4] + ws[5]);
        g_part[b * 5 + g] = blocksum;
        unsigned t = atomic_inc_release(&g_done);
        isLast = (t == (unsigned)(total - 1));
    }
    __syncthreads();

    if (isLast) {
        if (threadIdx.x == 0) {
            g_done = 0;
            __threadfence();
        }
        __syncthreads();
        __shared__ double sh[NT];
        const float4* __restrict__ pp = (const float4*)g_part;
        int n4 = total >> 2;
        double s = 0.0;
        for (int i = threadIdx.x; i < n4; i += NT) {
            float4 vv = __ldcg(pp + i);
            s += ((double)vv.x + (double)vv.y) + ((double)vv.z + (double)vv.w);
        }
        sh[threadIdx.x] = s;
        __syncthreads();
        if (threadIdx.x < 64) sh[threadIdx.x] += sh[threadIdx.x + 128];
        __syncthreads();
#pragma unroll
        for (int off = 64; off > 0; off >>= 1) {
            if (threadIdx.x < off) sh[threadIdx.x] += sh[threadIdx.x + off];
            __syncthreads();
        }
        if (threadIdx.x == 0) out[0] = (float)sh[0];
    }
}

extern "C" void kernel_launch(void* const* d_in, const int* in_sizes, int n_in,
                              void* d_out, int out_size) {
    const float* pred = (const float*)d_in[0];
    const float* tgt  = (const float*)d_in[1];
    int B = in_sizes[1] / 4;
    if (B > BMAX) B = BMAX;

    dim3 grid(5, B);
    main_kernel<<<grid, NT>>>(pred, tgt, (float*)d_out, B * 5);
}